// round 13
// baseline (speedup 1.0000x reference)
#include <cuda_runtime.h>
#include <cstdint>

// Problem constants
#define B_N   2048
#define C_N   128
#define E_N   10
#define KPN   80      // k-pair rows (160 k values, 10 k16 steps)
#define OUTW  512

// Folded, symmetrized, split-bf16 A (from prep):
// uint2 per (ec, kp, mj): x = bf16x2 hi (krow 2kp, 2kp+1), y = bf16x2 lo
__device__ __align__(16) uint32_t g_A[(size_t)E_N * C_N * KPN * 64 * 2];
__device__ int g_cnt[E_N];
__device__ int g_list[E_N * B_N];

// ---------------------------------------------------------------------------
__global__ void k_zero() {
    if (threadIdx.x < E_N) g_cnt[threadIdx.x] = 0;
}

__global__ void k_group(const float* __restrict__ y) {
    int b = blockIdx.x * blockDim.x + threadIdx.x;
    if (b >= B_N) return;
    int e = 0;
#pragma unroll
    for (int q = 0; q < E_N; q++)
        if (y[b * E_N + q] > 0.5f) e = q;
    int pos = atomicAdd(&g_cnt[e], 1);
    g_list[e * B_N + pos] = b;
}

// ---------------------------------------------------------------------------
__device__ __forceinline__ void split_pack(float v0, float v1,
                                           uint32_t& hiw, uint32_t& low) {
    uint32_t u0 = __float_as_uint(v0), u1 = __float_as_uint(v1);
    hiw = __byte_perm(u0, u1, 0x7632);
    float l0 = v0 - __uint_as_float(u0 & 0xffff0000u);
    float l1 = v1 - __uint_as_float(u1 & 0xffff0000u);
    asm("cvt.rn.bf16x2.f32 %0, %1, %2;" : "=r"(low) : "f"(l1), "f"(l0));
}

__device__ __forceinline__ void tri_li(int r, int& l, int& i) {
    l = 0;
    int rr = r;
    while (rr >= 16 - l) { rr -= 16 - l; l++; }
    i = l + rr;
}

// ---------------------------------------------------------------------------
// k_prep3 (unchanged from R9): fold element weights into split-bf16 A.
template <int K0, int K1>
__device__ void prep_compute(int kp, int jb,
                             const float* __restrict__ W0,
                             const float* __restrict__ W1,
                             const float* __restrict__ us0,
                             const float* __restrict__ us1,
                             float* __restrict__ Os, int tid)
{
    const int ec_l = tid & 31;
    const int slot = tid >> 5;
    const int h    = slot >> 2;
    const int mjg  = slot & 3;

    for (int ch8 = 0; ch8 < 8; ch8++) {
        const int ec = (jb * 8 + ch8) * 32 + ec_l;
        const int e = ec >> 7, c = ec & 127;
        unsigned long long acc[8];
#pragma unroll
        for (int q = 0; q < 8; q++) acc[q] = 0ull;

        if (mjg == 0) {
            const unsigned long long* u64 =
                (const unsigned long long*)(us0 + h * 384);
#pragma unroll
            for (int k = 0; k < K0; k++) {
                float wk = W0[(e * K0 + k) * 128 + c];
                unsigned long long wp;
                asm("mov.b64 %0, {%1,%1};" : "=l"(wp) : "f"(wk));
#pragma unroll
                for (int q = 0; q < 8; q++) {
                    unsigned long long u = u64[k * 8 + q];
                    asm("fma.rn.f32x2 %0, %1, %2, %0;"
                        : "+l"(acc[q]) : "l"(u), "l"(wp));
                }
            }
        } else {
            const int mb = (mjg - 1) * 16;
            const unsigned long long* u64 =
                (const unsigned long long*)(us1 + h * 1632 + mb);
#pragma unroll
            for (int k = 0; k < K1; k++) {
                float wk = W1[(e * K1 + k) * 128 + c];
                unsigned long long wp;
                asm("mov.b64 %0, {%1,%1};" : "=l"(wp) : "f"(wk));
#pragma unroll
                for (int q = 0; q < 8; q++) {
                    unsigned long long u = u64[k * 24 + q];
                    asm("fma.rn.f32x2 %0, %1, %2, %0;"
                        : "+l"(acc[q]) : "l"(u), "l"(wp));
                }
            }
        }
#pragma unroll
        for (int q = 0; q < 8; q++) {
            float o0, o1;
            asm("mov.b64 {%0,%1}, %2;" : "=f"(o0), "=f"(o1) : "l"(acc[q]));
            Os[ec_l * 130 + h * 64 + mjg * 16 + 2 * q]     = o0;
            Os[ec_l * 130 + h * 64 + mjg * 16 + 2 * q + 1] = o1;
        }
        __syncthreads();

        for (int widx = tid; widx < 2048; widx += 256) {
            int el = widx >> 6, mj = widx & 63;
            float o0 = Os[el * 130 + mj];
            float o1 = Os[el * 130 + 64 + mj];
            uint32_t hiw, low;
            split_pack(o0, o1, hiw, low);
            size_t gi = (((size_t)((jb * 8 + ch8) * 32 + el) * KPN + kp) * 64 + mj) * 2;
            *(uint2*)&g_A[gi] = make_uint2(hiw, low);
        }
        __syncthreads();
    }
}

__global__ void __launch_bounds__(256) k_prep3(
    const float* __restrict__ U3_0, const float* __restrict__ U2_0, const float* __restrict__ U1_0,
    const float* __restrict__ W3_0, const float* __restrict__ W2_0, const float* __restrict__ W1_0,
    const float* __restrict__ U3_1, const float* __restrict__ U2_1, const float* __restrict__ U1_1,
    const float* __restrict__ W3_1, const float* __restrict__ W2_1, const float* __restrict__ W1_1)
{
    __shared__ __align__(16) float us0[768];
    __shared__ __align__(16) float us1[3264];
    __shared__ float Os[32 * 130];

    const int kp = blockIdx.x, jb = blockIdx.y;
    const int tid = threadIdx.x;

    if (kp <= 67) {
        for (int h = 0; h < 2; h++) {
            int r = 2 * kp + h, l, i;
            tri_li(r, l, i);
            for (int idx = tid; idx < 23 * 16; idx += 256) {
                int k = idx >> 4, j = idx & 15;
                float v = U3_0[((i * 16 + j) * 16 + l) * 23 + k];
                if (l < i) v += U3_0[((l * 16 + j) * 16 + i) * 23 + k];
                us0[h * 384 + k * 16 + j] = v;
            }
            for (int idx = tid; idx < 33 * 48; idx += 256) {
                int k = idx / 48, mj = idx % 48, m = mj >> 4, j = mj & 15;
                float v = U3_1[(((m * 16 + i) * 16 + j) * 16 + l) * 33 + k];
                if (l < i) v += U3_1[(((m * 16 + l) * 16 + j) * 16 + i) * 33 + k];
                us1[h * 1632 + k * 48 + mj] = v;
            }
        }
        __syncthreads();
        prep_compute<23, 33>(kp, jb, W3_0, W3_1, us0, us1, Os, tid);
    } else if (kp <= 75) {
        for (int h = 0; h < 2; h++) {
            int j0 = 2 * kp + h - 136;
            for (int idx = tid; idx < 4 * 16; idx += 256) {
                int k = idx >> 4, j = idx & 15;
                us0[h * 384 + k * 16 + j] = U2_0[(j * 16 + j0) * 4 + k];
            }
            for (int idx = tid; idx < 5 * 48; idx += 256) {
                int k = idx / 48, mj = idx % 48, m = mj >> 4, j = mj & 15;
                us1[h * 1632 + k * 48 + mj] = U2_1[((m * 16 + j) * 16 + j0) * 5 + k];
            }
        }
        __syncthreads();
        prep_compute<4, 5>(kp, jb, W2_0, W2_1, us0, us1, Os, tid);
    } else {
        // kp 76: krow 152 = const (U1), 153 = 0. kp 77..79 -> zeros.
        for (int idx = tid; idx < 768; idx += 256) us0[idx] = 0.f;
        for (int idx = tid; idx < 3264; idx += 256) us1[idx] = 0.f;
        __syncthreads();
        if (kp == 76) {
            if (tid < 16) us0[tid] = U1_0[tid];
            if (tid < 48) us1[tid] = U1_1[tid];
        }
        __syncthreads();
        prep_compute<1, 1>(kp, jb, W1_0, W1_1, us0, us1, Os, tid);
    }
}

// ---------------------------------------------------------------------------
__device__ __forceinline__ void mma_bf16(float* d,
                                         uint32_t a0, uint32_t a1, uint32_t a2, uint32_t a3,
                                         uint32_t b0, uint32_t b1) {
    asm volatile(
        "mma.sync.aligned.m16n8k16.row.col.f32.bf16.bf16.f32 "
        "{%0,%1,%2,%3}, {%4,%5,%6,%7}, {%8,%9}, {%0,%1,%2,%3};"
        : "+f"(d[0]), "+f"(d[1]), "+f"(d[2]), "+f"(d[3])
        : "r"(a0), "r"(a1), "r"(a2), "r"(a3), "r"(b0), "r"(b1));
}

// smem byte offsets for k_main
#define OFF_A   0        // A image: 2560 uint4 = 40960 B
#define OFF_B   40960    // B image: 2560 uint4 = 40960 B
#define OFF_XS  81920    // float Xs[64][18] = 4608 B (rows 16=valid, 17=0)
#define OFF_NB  86528    // int Nb[64] = 256 B
#define OFF_LUT 86784    // uint32 lut[160] = 640 B
#define SMEM_SZ 87424    // x2 CTAs = 174,848 B

// k_main: per (c,e) CTA, 256 threads / 8 warps, 2 CTAs/SM.
// out4[64 mj x 64 n] = A[64 x 160] * B[160 x 64], split-bf16 (hh+hl+lh),
// fragment-major uint4 smem images (LDS.128), shuffle-reduced epilogue.
__global__ void __launch_bounds__(256, 2) k_main(const float* __restrict__ x,
                                                 float* __restrict__ out)
{
    extern __shared__ __align__(16) char smem[];
    float*    Xs  = (float*)(smem + OFF_XS);
    int*      Nb  = (int*)(smem + OFF_NB);
    uint32_t* lut = (uint32_t*)(smem + OFF_LUT);

    const int c = blockIdx.x, e = blockIdx.y;
    const int tid  = threadIdx.x;
    const int lane = tid & 31, warp = tid >> 5;
    const int gid  = lane >> 2, tig = lane & 3;
    const int wm   = warp & 3;     // output m / A m-tile
    const int nh   = warp >> 2;    // n half

    // --- krow -> (l, i) LUT, 16-bit packed ---
    if (tid < 160) {
        int pl, pi;
        if (tid < 136)       { int l, i; tri_li(tid, l, i); pl = l; pi = i; }
        else if (tid < 152)  { pl = tid - 136; pi = 16; }   // x_j * valid
        else if (tid == 152) { pl = 16; pi = 16; }          // valid^2
        else                 { pl = 17; pi = 17; }          // zero
        lut[tid] = (uint32_t)pl | ((uint32_t)pi << 16);
    }

    // --- A image init: fragment-major uint4 = (a_h, a_l, a'_h, a'_l) ---
    // uint4 index: ks*256 + half*128 + wm*32 + lane
    //   kp = ks*8 + half*4 + (lane&3),  mj = wm*16 + {gid, 8+gid}
    {
        const uint2* src = (const uint2*)&g_A[(size_t)(e * C_N + c) * KPN * 64 * 2];
        uint4* Ai = (uint4*)(smem + OFF_A);
        for (int idx = tid; idx < 2560; idx += 256) {
            int ks = idx >> 8, r = idx & 255;
            int half = r >> 7, r2 = r & 127;
            int wmt = r2 >> 5, ln = r2 & 31;
            int t = ln & 3, g = ln >> 2;
            int kp = ks * 8 + half * 4 + t;
            uint2 ua = src[kp * 64 + wmt * 16 + g];
            uint2 ub = src[kp * 64 + wmt * 16 + 8 + g];
            Ai[idx] = make_uint4(ua.x, ua.y, ub.x, ub.y);
        }
    }
    __syncthreads();

    const int cnt = g_cnt[e];
    const int* lst = &g_list[e * B_N];
    const int ntiles = (cnt + 63) >> 6;

    for (int t = 0; t < ntiles; t++) {
        __syncthreads();   // previous tile fully consumed (Xs/B/Nb)

        // --- Xs / Nb fill ---
        if (tid < 64) {
            const int idx = t * 64 + tid;
            float4 v0, v1, v2, v3;
            float vld;
            int b;
            if (idx < cnt) {
                b = lst[idx];
                const float4* xp = (const float4*)&x[((size_t)b * C_N + c) * 16];
                v0 = xp[0]; v1 = xp[1]; v2 = xp[2]; v3 = xp[3];
                vld = 1.f;
            } else {
                v0 = v1 = v2 = v3 = make_float4(0.f, 0.f, 0.f, 0.f);
                vld = 0.f; b = -1;
            }
            float* xr = Xs + tid * 18;
            xr[0]  = v0.x; xr[1]  = v0.y; xr[2]  = v0.z; xr[3]  = v0.w;
            xr[4]  = v1.x; xr[5]  = v1.y; xr[6]  = v1.z; xr[7]  = v1.w;
            xr[8]  = v2.x; xr[9]  = v2.y; xr[10] = v2.z; xr[11] = v2.w;
            xr[12] = v3.x; xr[13] = v3.y; xr[14] = v3.z; xr[15] = v3.w;
            xr[16] = vld;  xr[17] = 0.f;
            Nb[tid] = b;
        }
        __syncthreads();

        // --- B build, fragment-major, conflict-free STS.64 ---
        // element (kp, n) -> word addr: ko*1024 + p*128 + ord*4 + h*2
        //   ko=kp>>3, p=n>>3, ord=(4*(n&7) + (kp&3) + 4*p)&31, h=(kp>>2)&1
#pragma unroll 5
        for (int it = 0; it < 20; it++) {
            const int s  = warp * 20 + it;       // 0..159
            const int ko = s >> 4, nq = s & 15;
            const int p  = nq >> 1, gb = (nq & 1) * 4;
            const int kp = ko * 8 + (lane & 7);
            const int n  = p * 8 + gb + (lane >> 3);
            const uint32_t lu0 = lut[2 * kp], lu1 = lut[2 * kp + 1];
            const float* xr = Xs + n * 18;
            float v0 = xr[lu0 & 0xffff] * xr[lu0 >> 16];
            float v1 = xr[lu1 & 0xffff] * xr[lu1 >> 16];
            uint32_t hiw, low;
            split_pack(v0, v1, hiw, low);
            const int g = n & 7, tt = kp & 3, h = (kp >> 2) & 1;
            const int ord = (4 * g + tt + 4 * p) & 31;
            *(uint2*)(smem + OFF_B + (ko * 1024 + p * 128 + ord * 4 + h * 2) * 4)
                = make_uint2(hiw, low);
        }
        __syncthreads();

        // --- GEMM: 10 k16-steps, per step 6 LDS.128 + 12 HMMA ---
        float d[4][4];
#pragma unroll
        for (int nf = 0; nf < 4; nf++)
#pragma unroll
            for (int q = 0; q < 4; q++) d[nf][q] = 0.f;

#pragma unroll
        for (int ks = 0; ks < 10; ks++) {
            uint4 U0 = *(uint4*)(smem + OFF_A + (ks * 1024 + wm * 128 + lane * 4) * 4);
            uint4 U1 = *(uint4*)(smem + OFF_A + (ks * 1024 + 512 + wm * 128 + lane * 4) * 4);
#pragma unroll
            for (int nf = 0; nf < 4; nf++) {
                const int p = nh * 4 + nf;
                uint4 V = *(uint4*)(smem + OFF_B +
                                    (ks * 1024 + p * 128 + ((lane + 4 * p) & 31) * 4) * 4);
                mma_bf16(d[nf], U0.x, U0.z, U1.x, U1.z, V.x, V.z);  // hh
                mma_bf16(d[nf], U0.x, U0.z, U1.x, U1.z, V.y, V.w);  // hl
                mma_bf16(d[nf], U0.y, U0.w, U1.y, U1.w, V.x, V.z);  // lh
            }
        }

        // --- epilogue: out[m=wm, n] = sum_j C[16wm+j][n] * x_j[n] ---
        // thread holds C rows j=gid, 8+gid; reduce over gid via shfl.bfly.
        const int col = (wm == 0) ? c : (128 + c * 3 + (wm - 1));
#pragma unroll
        for (int nf = 0; nf < 4; nf++) {
            const int nn = nh * 32 + nf * 8 + 2 * tig;
            float p0 = d[nf][0] * Xs[nn * 18 + gid]
                     + d[nf][2] * Xs[nn * 18 + 8 + gid];
            float p1 = d[nf][1] * Xs[(nn + 1) * 18 + gid]
                     + d[nf][3] * Xs[(nn + 1) * 18 + 8 + gid];
#pragma unroll
            for (int off = 4; off <= 16; off <<= 1) {
                p0 += __shfl_xor_sync(0xffffffffu, p0, off);
                p1 += __shfl_xor_sync(0xffffffffu, p1, off);
            }
            if (gid == 0) {
                const int b0 = Nb[nn], b1 = Nb[nn + 1];
                if (b0 >= 0) out[b0 * OUTW + col] = p0;
                if (b1 >= 0) out[b1 * OUTW + col] = p1;
            }
        }
    }
}

// ---------------------------------------------------------------------------
extern "C" void kernel_launch(void* const* d_in, const int* in_sizes, int n_in,
                              void* d_out, int out_size)
{
    (void)in_sizes; (void)n_in; (void)out_size;
    const float* x    = (const float*)d_in[0];
    const float* y    = (const float*)d_in[1];
    const float* U3_0 = (const float*)d_in[2];
    const float* U2_0 = (const float*)d_in[3];
    const float* U1_0 = (const float*)d_in[4];
    const float* W3_0 = (const float*)d_in[5];
    const float* W2_0 = (const float*)d_in[6];
    const float* W1_0 = (const float*)d_in[7];
    const float* U3_1 = (const float*)d_in[8];
    const float* U2_1 = (const float*)d_in[9];
    const float* U1_1 = (const float*)d_in[10];
    const float* W3_1 = (const float*)d_in[11];
    const float* W2_1 = (const float*)d_in[12];
    const float* W1_1 = (const float*)d_in[13];

    cudaFuncSetAttribute(k_main, cudaFuncAttributeMaxDynamicSharedMemorySize, SMEM_SZ);

    k_zero<<<1, 32>>>();
    k_group<<<(B_N + 255) / 256, 256>>>(y);
    k_prep3<<<dim3(KPN, 5), 256>>>(U3_0, U2_0, U1_0, W3_0, W2_0, W1_0,
                                   U3_1, U2_1, U1_1, W3_1, W2_1, W1_1);
    k_main<<<dim3(C_N, E_N), 256, SMEM_SZ>>>(x, (float*)d_out);
}

// round 14
// speedup vs baseline: 1.2957x; 1.2957x over previous
#include <cuda_runtime.h>
#include <cuda_fp16.h>
#include <cstdint>

// Problem constants
#define B_N   2048
#define C_N   128
#define E_N   10
#define KPN   80      // k-pair rows (160 k values, 10 k16 steps)
#define AST   72      // float stride for Xs / Cs / B rows
#define OUTW  512

// Folded, symmetrized, split-fp16 A:
// uint2 per (ec, kp, mj): x = f16x2 hi (krow 2kp, 2kp+1), y = f16x2 lo residual
__device__ __align__(16) uint32_t g_A[(size_t)E_N * C_N * KPN * 64 * 2];
__device__ int g_cnt[E_N];
__device__ int g_list[E_N * B_N];

// ---------------------------------------------------------------------------
__global__ void k_zero() {
    if (threadIdx.x < E_N) g_cnt[threadIdx.x] = 0;
}

__global__ void k_group(const float* __restrict__ y) {
    int b = blockIdx.x * blockDim.x + threadIdx.x;
    if (b >= B_N) return;
    int e = 0;
#pragma unroll
    for (int q = 0; q < E_N; q++)
        if (y[b * E_N + q] > 0.5f) e = q;
    int pos = atomicAdd(&g_cnt[e], 1);
    g_list[e * B_N + pos] = b;
}

// ---------------------------------------------------------------------------
// fp16 split: hi = rn-f16(v), lo = rn-f16(v - hi). A = hi + lo to ~2^-23.
__device__ __forceinline__ void split_pack_f16(float v0, float v1,
                                               uint32_t& hiw, uint32_t& low) {
    asm("cvt.rn.f16x2.f32 %0, %1, %2;" : "=r"(hiw) : "f"(v1), "f"(v0));
    float h0 = __half2float(__ushort_as_half((unsigned short)(hiw & 0xffff)));
    float h1 = __half2float(__ushort_as_half((unsigned short)(hiw >> 16)));
    float l0 = v0 - h0, l1 = v1 - h1;
    asm("cvt.rn.f16x2.f32 %0, %1, %2;" : "=r"(low) : "f"(l1), "f"(l0));
}

__device__ __forceinline__ void tri_li(int r, int& l, int& i) {
    l = 0;
    int rr = r;
    while (rr >= 16 - l) { rr -= 16 - l; l++; }
    i = l + rr;
}

// ---------------------------------------------------------------------------
// k_prep3: fold element weights into split-fp16 A (same math as R9).
template <int K0, int K1>
__device__ void prep_compute(int kp, int jb,
                             const float* __restrict__ W0,
                             const float* __restrict__ W1,
                             const float* __restrict__ us0,
                             const float* __restrict__ us1,
                             float* __restrict__ Os, int tid)
{
    const int ec_l = tid & 31;
    const int slot = tid >> 5;
    const int h    = slot >> 2;     // krow half
    const int mjg  = slot & 3;      // 0: irrep0 (mj 0..15), 1..3: irrep1

    for (int ch8 = 0; ch8 < 8; ch8++) {
        const int ec = (jb * 8 + ch8) * 32 + ec_l;
        const int e = ec >> 7, c = ec & 127;
        unsigned long long acc[8];
#pragma unroll
        for (int q = 0; q < 8; q++) acc[q] = 0ull;

        if (mjg == 0) {
            const unsigned long long* u64 =
                (const unsigned long long*)(us0 + h * 384);
#pragma unroll
            for (int k = 0; k < K0; k++) {
                float wk = W0[(e * K0 + k) * 128 + c];
                unsigned long long wp;
                asm("mov.b64 %0, {%1,%1};" : "=l"(wp) : "f"(wk));
#pragma unroll
                for (int q = 0; q < 8; q++) {
                    unsigned long long u = u64[k * 8 + q];
                    asm("fma.rn.f32x2 %0, %1, %2, %0;"
                        : "+l"(acc[q]) : "l"(u), "l"(wp));
                }
            }
        } else {
            const int mb = (mjg - 1) * 16;
            const unsigned long long* u64 =
                (const unsigned long long*)(us1 + h * 1632 + mb);
#pragma unroll
            for (int k = 0; k < K1; k++) {
                float wk = W1[(e * K1 + k) * 128 + c];
                unsigned long long wp;
                asm("mov.b64 %0, {%1,%1};" : "=l"(wp) : "f"(wk));
#pragma unroll
                for (int q = 0; q < 8; q++) {
                    unsigned long long u = u64[k * 24 + q];
                    asm("fma.rn.f32x2 %0, %1, %2, %0;"
                        : "+l"(acc[q]) : "l"(u), "l"(wp));
                }
            }
        }
#pragma unroll
        for (int q = 0; q < 8; q++) {
            float o0, o1;
            asm("mov.b64 {%0,%1}, %2;" : "=f"(o0), "=f"(o1) : "l"(acc[q]));
            Os[ec_l * 130 + h * 64 + mjg * 16 + 2 * q]     = o0;
            Os[ec_l * 130 + h * 64 + mjg * 16 + 2 * q + 1] = o1;
        }
        __syncthreads();

        for (int widx = tid; widx < 2048; widx += 256) {
            int el = widx >> 6, mj = widx & 63;
            float o0 = Os[el * 130 + mj];
            float o1 = Os[el * 130 + 64 + mj];
            uint32_t hiw, low;
            split_pack_f16(o0, o1, hiw, low);
            size_t gi = (((size_t)((jb * 8 + ch8) * 32 + el) * KPN + kp) * 64 + mj) * 2;
            *(uint2*)&g_A[gi] = make_uint2(hiw, low);
        }
        __syncthreads();
    }
}

__global__ void __launch_bounds__(256) k_prep3(
    const float* __restrict__ U3_0, const float* __restrict__ U2_0, const float* __restrict__ U1_0,
    const float* __restrict__ W3_0, const float* __restrict__ W2_0, const float* __restrict__ W1_0,
    const float* __restrict__ U3_1, const float* __restrict__ U2_1, const float* __restrict__ U1_1,
    const float* __restrict__ W3_1, const float* __restrict__ W2_1, const float* __restrict__ W1_1)
{
    __shared__ __align__(16) float us0[768];
    __shared__ __align__(16) float us1[3264];
    __shared__ float Os[32 * 130];

    const int kp = blockIdx.x, jb = blockIdx.y;
    const int tid = threadIdx.x;

    if (kp <= 67) {
        for (int h = 0; h < 2; h++) {
            int r = 2 * kp + h, l, i;
            tri_li(r, l, i);
            for (int idx = tid; idx < 23 * 16; idx += 256) {
                int k = idx >> 4, j = idx & 15;
                float v = U3_0[((i * 16 + j) * 16 + l) * 23 + k];
                if (l < i) v += U3_0[((l * 16 + j) * 16 + i) * 23 + k];
                us0[h * 384 + k * 16 + j] = v;
            }
            for (int idx = tid; idx < 33 * 48; idx += 256) {
                int k = idx / 48, mj = idx % 48, m = mj >> 4, j = mj & 15;
                float v = U3_1[(((m * 16 + i) * 16 + j) * 16 + l) * 33 + k];
                if (l < i) v += U3_1[(((m * 16 + l) * 16 + j) * 16 + i) * 33 + k];
                us1[h * 1632 + k * 48 + mj] = v;
            }
        }
        __syncthreads();
        prep_compute<23, 33>(kp, jb, W3_0, W3_1, us0, us1, Os, tid);
    } else if (kp <= 75) {
        for (int h = 0; h < 2; h++) {
            int j0 = 2 * kp + h - 136;
            for (int idx = tid; idx < 4 * 16; idx += 256) {
                int k = idx >> 4, j = idx & 15;
                us0[h * 384 + k * 16 + j] = U2_0[(j * 16 + j0) * 4 + k];
            }
            for (int idx = tid; idx < 5 * 48; idx += 256) {
                int k = idx / 48, mj = idx % 48, m = mj >> 4, j = mj & 15;
                us1[h * 1632 + k * 48 + mj] = U2_1[((m * 16 + j) * 16 + j0) * 5 + k];
            }
        }
        __syncthreads();
        prep_compute<4, 5>(kp, jb, W2_0, W2_1, us0, us1, Os, tid);
    } else {
        // kp 76: krow 152 = const (U1), 153 = 0. kp 77..79 -> zeros.
        for (int idx = tid; idx < 768; idx += 256) us0[idx] = 0.f;
        for (int idx = tid; idx < 3264; idx += 256) us1[idx] = 0.f;
        __syncthreads();
        if (kp == 76) {
            if (tid < 16) us0[tid] = U1_0[tid];
            if (tid < 48) us1[tid] = U1_1[tid];
        }
        __syncthreads();
        prep_compute<1, 1>(kp, jb, W1_0, W1_1, us0, us1, Os, tid);
    }
}

// ---------------------------------------------------------------------------
__device__ __forceinline__ void mma_f16(float* d,
                                        uint32_t a0, uint32_t a1, uint32_t a2, uint32_t a3,
                                        uint32_t b0, uint32_t b1) {
    asm volatile(
        "mma.sync.aligned.m16n8k16.row.col.f32.f16.f16.f32 "
        "{%0,%1,%2,%3}, {%4,%5,%6,%7}, {%8,%9}, {%0,%1,%2,%3};"
        : "+f"(d[0]), "+f"(d[1]), "+f"(d[2]), "+f"(d[3])
        : "r"(a0), "r"(a1), "r"(a2), "r"(a3), "r"(b0), "r"(b1));
}

// smem word offsets for k_main (uint32 units)
#define SM_A   0                       // 80 * 128 = 10240 (uint2 hi/lo, rotated)
#define SM_B   10240                   // 80 * 72 = 5760 (single f16x2 word)
#define SM_X   16000                   // 18 * 72 floats = 1296
#define SM_C   17296                   // 64 * 72 floats = 4608
#define SM_LUT 21904                   // 160 words
#define SM_WORDS 22064                 // 88,256 B -> 2 CTAs/SM

// k_main: per (c, e) CTA, 256 threads / 8 warps, 2 CTAs/SM.
// out4[64 x 64] = A[64 x 160] * B[160 x 64], split-fp16 A (hi+lo), fp16 B.
// A smem: word addr = kp*128 + ((col + 4*(kp&3)) & 63)*2 + sel (hi/lo).
// B smem: word addr = kp*72 + n  (stride 72 -> conflict-free fragments).
__global__ void __launch_bounds__(256, 2) k_main(const float* __restrict__ x,
                                                 float* __restrict__ out)
{
    extern __shared__ uint32_t sm[];
    uint32_t* Aw  = sm + SM_A;
    uint32_t* Bw  = sm + SM_B;
    float*    Xs  = (float*)(sm + SM_X);   // rows 0..15 = x, 16 = valid, 17 = 0
    float*    Cs  = (float*)(sm + SM_C);
    uint32_t* lut = sm + SM_LUT;           // (pl | pi<<16) per krow

    const int c = blockIdx.x, e = blockIdx.y;
    const int tid  = threadIdx.x;
    const int lane = tid & 31, warp = tid >> 5;
    const int gid  = lane >> 2, tig = lane & 3;
    const int m_base = (warp & 3) * 16;
    const int n_base = (warp >> 2) * 32;

    // --- one-time init: LUT, zero row, A tile load (swizzled) ---
    if (tid < 160) {
        int pl, pi;
        if (tid < 136)      { int l, i; tri_li(tid, l, i); pl = l; pi = i; }
        else if (tid < 152) { pl = tid - 136; pi = 16; }
        else if (tid == 152){ pl = 16; pi = 16; }
        else                { pl = 17; pi = 17; }
        lut[tid] = (uint32_t)pl | ((uint32_t)pi << 16);
    }
    if (tid < AST) Xs[17 * AST + tid] = 0.f;
    {
        const uint4* srcA = (const uint4*)&g_A[(size_t)(e * C_N + c) * (KPN * 128)];
        for (int idx = tid; idx < KPN * 32; idx += 256) {
            int kp = idx >> 5, mp = idx & 31;          // mj pair index
            int mjp = (mp * 2 + 4 * (kp & 3)) & 63;    // rotated (stays even)
            *(uint4*)&Aw[kp * 128 + mjp * 2] = srcA[idx];
        }
    }

    const int cnt = g_cnt[e];
    const int* lst = &g_list[e * B_N];
    const int ntiles = (cnt + 63) >> 6;

    const int n   = tid & 63;
    const int grp = tid >> 6;     // 4 groups x 20 kp rows

    for (int t = 0; t < ntiles; t++) {
        __syncthreads();   // init / previous tile fully consumed

        // --- phase 0: grp 0 fills Xs ---
        if (grp == 0) {
            const int idx = t * 64 + n;
            float4 v0, v1, v2, v3;
            float vld;
            if (idx < cnt) {
                const float4* xp = (const float4*)&x[((size_t)lst[idx] * C_N + c) * 16];
                v0 = xp[0]; v1 = xp[1]; v2 = xp[2]; v3 = xp[3];
                vld = 1.f;
            } else {
                v0 = v1 = v2 = v3 = make_float4(0.f, 0.f, 0.f, 0.f);
                vld = 0.f;
            }
            Xs[0*AST+n]=v0.x;  Xs[1*AST+n]=v0.y;  Xs[2*AST+n]=v0.z;  Xs[3*AST+n]=v0.w;
            Xs[4*AST+n]=v1.x;  Xs[5*AST+n]=v1.y;  Xs[6*AST+n]=v1.z;  Xs[7*AST+n]=v1.w;
            Xs[8*AST+n]=v2.x;  Xs[9*AST+n]=v2.y;  Xs[10*AST+n]=v2.z; Xs[11*AST+n]=v2.w;
            Xs[12*AST+n]=v3.x; Xs[13*AST+n]=v3.y; Xs[14*AST+n]=v3.z; Xs[15*AST+n]=v3.w;
            Xs[16*AST+n]=vld;
        }
        __syncthreads();

        // --- phase 1: build fp16 B (20 kp rows per thread) ---
#pragma unroll 5
        for (int s = 0; s < 20; s++) {
            const int kp = grp * 20 + s;
            const uint32_t lu0 = lut[2 * kp], lu1 = lut[2 * kp + 1];
            float v0 = Xs[(lu0 & 0xffff) * AST + n] * Xs[(lu0 >> 16) * AST + n];
            float v1 = Xs[(lu1 & 0xffff) * AST + n] * Xs[(lu1 >> 16) * AST + n];
            uint32_t bw;
            asm("cvt.rn.f16x2.f32 %0, %1, %2;" : "=r"(bw) : "f"(v1), "f"(v0));
            Bw[kp * AST + n] = bw;
        }
        __syncthreads();

        // --- tensor GEMM: 10 k16-steps, (Ah + Al) * B = 8 MMA/step ---
        float d[4][4];
#pragma unroll
        for (int nf = 0; nf < 4; nf++)
#pragma unroll
            for (int q = 0; q < 4; q++) d[nf][q] = 0.f;

        const int mjA0 = ((m_base + gid + 4 * tig) & 63) * 2;
        const int mjA1 = ((m_base + 8 + gid + 4 * tig) & 63) * 2;
#pragma unroll
        for (int ks = 0; ks < 10; ks++) {
            const int rA0 = (ks * 8 + tig) * 128;
            const int rA1 = (ks * 8 + 4 + tig) * 128;
            uint2 a0p = *(uint2*)&Aw[rA0 + mjA0];
            uint2 a1p = *(uint2*)&Aw[rA0 + mjA1];
            uint2 a2p = *(uint2*)&Aw[rA1 + mjA0];
            uint2 a3p = *(uint2*)&Aw[rA1 + mjA1];
            const int rB0 = (ks * 8 + tig) * AST;
            const int rB1 = (ks * 8 + 4 + tig) * AST;
#pragma unroll
            for (int nf = 0; nf < 4; nf++) {
                const int nn = n_base + nf * 8 + gid;
                uint32_t b0 = Bw[rB0 + nn];
                uint32_t b1 = Bw[rB1 + nn];
                mma_f16(d[nf], a0p.x, a1p.x, a2p.x, a3p.x, b0, b1);  // hi
                mma_f16(d[nf], a0p.y, a1p.y, a2p.y, a3p.y, b0, b1);  // lo
            }
        }

        // --- stash C ---
#pragma unroll
        for (int nf = 0; nf < 4; nf++) {
            const int nn = n_base + nf * 8 + 2 * tig;
            *(float2*)&Cs[(m_base + gid) * AST + nn]     = make_float2(d[nf][0], d[nf][1]);
            *(float2*)&Cs[(m_base + 8 + gid) * AST + nn] = make_float2(d[nf][2], d[nf][3]);
        }
        __syncthreads();

        // --- epilogue: out[m,n] = sum_j C[m*16+j,n] * x_j[n] ---
        {
            const int m = tid >> 6;
            const int idx = t * 64 + n;
            if (idx < cnt) {
                float s = 0.f;
#pragma unroll
                for (int j = 0; j < 16; j++)
                    s += Cs[(m * 16 + j) * AST + n] * Xs[j * AST + n];
                const int b = lst[idx];
                const int col = (m == 0) ? c : (128 + c * 3 + (m - 1));
                out[b * OUTW + col] = s;
            }
        }
    }
}

// ---------------------------------------------------------------------------
extern "C" void kernel_launch(void* const* d_in, const int* in_sizes, int n_in,
                              void* d_out, int out_size)
{
    (void)in_sizes; (void)n_in; (void)out_size;
    const float* x    = (const float*)d_in[0];
    const float* y    = (const float*)d_in[1];
    const float* U3_0 = (const float*)d_in[2];
    const float* U2_0 = (const float*)d_in[3];
    const float* U1_0 = (const float*)d_in[4];
    const float* W3_0 = (const float*)d_in[5];
    const float* W2_0 = (const float*)d_in[6];
    const float* W1_0 = (const float*)d_in[7];
    const float* U3_1 = (const float*)d_in[8];
    const float* U2_1 = (const float*)d_in[9];
    const float* U1_1 = (const float*)d_in[10];
    const float* W3_1 = (const float*)d_in[11];
    const float* W2_1 = (const float*)d_in[12];
    const float* W1_1 = (const float*)d_in[13];

    const int smem_main = SM_WORDS * (int)sizeof(uint32_t);  // 88,256 B
    cudaFuncSetAttribute(k_main, cudaFuncAttributeMaxDynamicSharedMemorySize, smem_main);

    k_zero<<<1, 32>>>();
    k_group<<<(B_N + 255) / 256, 256>>>(y);
    k_prep3<<<dim3(KPN, 5), 256>>>(U3_0, U2_0, U1_0, W3_0, W2_0, W1_0,
                                   U3_1, U2_1, U1_1, W3_1, W2_1, W1_1);
    k_main<<<dim3(C_N, E_N), 256, smem_main>>>(x, (float*)d_out);
}

// round 16
// speedup vs baseline: 1.2973x; 1.0012x over previous
#include <cuda_runtime.h>
#include <cuda_fp16.h>
#include <cstdint>

// Problem constants
#define B_N   2048
#define C_N   128
#define E_N   10
#define KPN   80      // k-pair rows (160 k values, 10 k16 steps)
#define AST   72      // word stride for B rows / float stride for Cs
#define OUTW  512

// Folded, symmetrized, split-fp16 A:
// uint2 per (ec, kp, mj): x = f16x2 hi (krow 2kp, 2kp+1), y = f16x2 lo residual
__device__ __align__(16) uint32_t g_A[(size_t)E_N * C_N * KPN * 64 * 2];
__device__ int g_cnt[E_N];
__device__ int g_list[E_N * B_N];

// ---------------------------------------------------------------------------
__global__ void k_zero() {
    if (threadIdx.x < E_N) g_cnt[threadIdx.x] = 0;
}

__global__ void k_group(const float* __restrict__ y) {
    int b = blockIdx.x * blockDim.x + threadIdx.x;
    if (b >= B_N) return;
    int e = 0;
#pragma unroll
    for (int q = 0; q < E_N; q++)
        if (y[b * E_N + q] > 0.5f) e = q;
    int pos = atomicAdd(&g_cnt[e], 1);
    g_list[e * B_N + pos] = b;
}

// ---------------------------------------------------------------------------
// fp16 split: hi = rn-f16(v), lo = rn-f16(v - hi). A = hi + lo to ~2^-23.
__device__ __forceinline__ void split_pack_f16(float v0, float v1,
                                               uint32_t& hiw, uint32_t& low) {
    asm("cvt.rn.f16x2.f32 %0, %1, %2;" : "=r"(hiw) : "f"(v1), "f"(v0));
    float h0 = __half2float(__ushort_as_half((unsigned short)(hiw & 0xffff)));
    float h1 = __half2float(__ushort_as_half((unsigned short)(hiw >> 16)));
    float l0 = v0 - h0, l1 = v1 - h1;
    asm("cvt.rn.f16x2.f32 %0, %1, %2;" : "=r"(low) : "f"(l1), "f"(l0));
}

__device__ __forceinline__ void tri_li(int r, int& l, int& i) {
    l = 0;
    int rr = r;
    while (rr >= 16 - l) { rr -= 16 - l; l++; }
    i = l + rr;
}

// Compile-time krow -> (l, i) mapping (same enumeration as tri_li + tails)
__host__ __device__ constexpr int ct_tri_l(int r) {
    int l = 0;
    while (r >= 16 - l) { r -= 16 - l; l++; }
    return l;
}
__host__ __device__ constexpr int ct_tri_i(int r) {
    int l = 0;
    while (r >= 16 - l) { r -= 16 - l; l++; }
    return l + r;
}
__host__ __device__ constexpr int row_l(int r) {
    return r < 136 ? ct_tri_l(r) : (r < 152 ? r - 136 : (r == 152 ? 16 : 17));
}
__host__ __device__ constexpr int row_i(int r) {
    return r < 136 ? ct_tri_i(r) : (r < 152 ? 16 : (r == 152 ? 16 : 17));
}

// ---------------------------------------------------------------------------
// k_prep3 (unchanged from R14): fold element weights into split-fp16 A.
template <int K0, int K1>
__device__ void prep_compute(int kp, int jb,
                             const float* __restrict__ W0,
                             const float* __restrict__ W1,
                             const float* __restrict__ us0,
                             const float* __restrict__ us1,
                             float* __restrict__ Os, int tid)
{
    const int ec_l = tid & 31;
    const int slot = tid >> 5;
    const int h    = slot >> 2;
    const int mjg  = slot & 3;

    for (int ch8 = 0; ch8 < 8; ch8++) {
        const int ec = (jb * 8 + ch8) * 32 + ec_l;
        const int e = ec >> 7, c = ec & 127;
        unsigned long long acc[8];
#pragma unroll
        for (int q = 0; q < 8; q++) acc[q] = 0ull;

        if (mjg == 0) {
            const unsigned long long* u64 =
                (const unsigned long long*)(us0 + h * 384);
#pragma unroll
            for (int k = 0; k < K0; k++) {
                float wk = W0[(e * K0 + k) * 128 + c];
                unsigned long long wp;
                asm("mov.b64 %0, {%1,%1};" : "=l"(wp) : "f"(wk));
#pragma unroll
                for (int q = 0; q < 8; q++) {
                    unsigned long long u = u64[k * 8 + q];
                    asm("fma.rn.f32x2 %0, %1, %2, %0;"
                        : "+l"(acc[q]) : "l"(u), "l"(wp));
                }
            }
        } else {
            const int mb = (mjg - 1) * 16;
            const unsigned long long* u64 =
                (const unsigned long long*)(us1 + h * 1632 + mb);
#pragma unroll
            for (int k = 0; k < K1; k++) {
                float wk = W1[(e * K1 + k) * 128 + c];
                unsigned long long wp;
                asm("mov.b64 %0, {%1,%1};" : "=l"(wp) : "f"(wk));
#pragma unroll
                for (int q = 0; q < 8; q++) {
                    unsigned long long u = u64[k * 24 + q];
                    asm("fma.rn.f32x2 %0, %1, %2, %0;"
                        : "+l"(acc[q]) : "l"(u), "l"(wp));
                }
            }
        }
#pragma unroll
        for (int q = 0; q < 8; q++) {
            float o0, o1;
            asm("mov.b64 {%0,%1}, %2;" : "=f"(o0), "=f"(o1) : "l"(acc[q]));
            Os[ec_l * 130 + h * 64 + mjg * 16 + 2 * q]     = o0;
            Os[ec_l * 130 + h * 64 + mjg * 16 + 2 * q + 1] = o1;
        }
        __syncthreads();

        for (int widx = tid; widx < 2048; widx += 256) {
            int el = widx >> 6, mj = widx & 63;
            float o0 = Os[el * 130 + mj];
            float o1 = Os[el * 130 + 64 + mj];
            uint32_t hiw, low;
            split_pack_f16(o0, o1, hiw, low);
            size_t gi = (((size_t)((jb * 8 + ch8) * 32 + el) * KPN + kp) * 64 + mj) * 2;
            *(uint2*)&g_A[gi] = make_uint2(hiw, low);
        }
        __syncthreads();
    }
}

__global__ void __launch_bounds__(256) k_prep3(
    const float* __restrict__ U3_0, const float* __restrict__ U2_0, const float* __restrict__ U1_0,
    const float* __restrict__ W3_0, const float* __restrict__ W2_0, const float* __restrict__ W1_0,
    const float* __restrict__ U3_1, const float* __restrict__ U2_1, const float* __restrict__ U1_1,
    const float* __restrict__ W3_1, const float* __restrict__ W2_1, const float* __restrict__ W1_1)
{
    __shared__ __align__(16) float us0[768];
    __shared__ __align__(16) float us1[3264];
    __shared__ float Os[32 * 130];

    const int kp = blockIdx.x, jb = blockIdx.y;
    const int tid = threadIdx.x;

    if (kp <= 67) {
        for (int h = 0; h < 2; h++) {
            int r = 2 * kp + h, l, i;
            tri_li(r, l, i);
            for (int idx = tid; idx < 23 * 16; idx += 256) {
                int k = idx >> 4, j = idx & 15;
                float v = U3_0[((i * 16 + j) * 16 + l) * 23 + k];
                if (l < i) v += U3_0[((l * 16 + j) * 16 + i) * 23 + k];
                us0[h * 384 + k * 16 + j] = v;
            }
            for (int idx = tid; idx < 33 * 48; idx += 256) {
                int k = idx / 48, mj = idx % 48, m = mj >> 4, j = mj & 15;
                float v = U3_1[(((m * 16 + i) * 16 + j) * 16 + l) * 33 + k];
                if (l < i) v += U3_1[(((m * 16 + l) * 16 + j) * 16 + i) * 33 + k];
                us1[h * 1632 + k * 48 + mj] = v;
            }
        }
        __syncthreads();
        prep_compute<23, 33>(kp, jb, W3_0, W3_1, us0, us1, Os, tid);
    } else if (kp <= 75) {
        for (int h = 0; h < 2; h++) {
            int j0 = 2 * kp + h - 136;
            for (int idx = tid; idx < 4 * 16; idx += 256) {
                int k = idx >> 4, j = idx & 15;
                us0[h * 384 + k * 16 + j] = U2_0[(j * 16 + j0) * 4 + k];
            }
            for (int idx = tid; idx < 5 * 48; idx += 256) {
                int k = idx / 48, mj = idx % 48, m = mj >> 4, j = mj & 15;
                us1[h * 1632 + k * 48 + mj] = U2_1[((m * 16 + j) * 16 + j0) * 5 + k];
            }
        }
        __syncthreads();
        prep_compute<4, 5>(kp, jb, W2_0, W2_1, us0, us1, Os, tid);
    } else {
        // kp 76: krow 152 = const (U1), 153 = 0. kp 77..79 -> zeros.
        for (int idx = tid; idx < 768; idx += 256) us0[idx] = 0.f;
        for (int idx = tid; idx < 3264; idx += 256) us1[idx] = 0.f;
        __syncthreads();
        if (kp == 76) {
            if (tid < 16) us0[tid] = U1_0[tid];
            if (tid < 48) us1[tid] = U1_1[tid];
        }
        __syncthreads();
        prep_compute<1, 1>(kp, jb, W1_0, W1_1, us0, us1, Os, tid);
    }
}

// ---------------------------------------------------------------------------
__device__ __forceinline__ void mma_f16(float* d,
                                        uint32_t a0, uint32_t a1, uint32_t a2, uint32_t a3,
                                        uint32_t b0, uint32_t b1) {
    asm volatile(
        "mma.sync.aligned.m16n8k16.row.col.f32.f16.f16.f32 "
        "{%0,%1,%2,%3}, {%4,%5,%6,%7}, {%8,%9}, {%0,%1,%2,%3};"
        : "+f"(d[0]), "+f"(d[1]), "+f"(d[2]), "+f"(d[3])
        : "r"(a0), "r"(a1), "r"(a2), "r"(a3), "r"(b0), "r"(b1));
}

// smem word offsets for k_main (uint32 units)
#define SM_A   0                       // 80 * 128 = 10240 (uint2 hi/lo, rotated)
#define SM_B   10240                   // 80 * 72 = 5760 (single f16x2 word)
#define SM_C   16000                   // 64 * 72 floats = 4608
#define SM_WORDS 20608                 // 82,432 B -> 2 CTAs/SM

// B-build step: compile-time (l,i) indices, zero LDS.
#define BSTEP(kpv) { \
    constexpr int _r0 = 2 * (kpv), _r1 = 2 * (kpv) + 1; \
    constexpr int _a0 = row_l(_r0), _b0 = row_i(_r0); \
    constexpr int _a1 = row_l(_r1), _b1 = row_i(_r1); \
    float _v0 = xr[_a0] * xr[_b0]; \
    float _v1 = xr[_a1] * xr[_b1]; \
    uint32_t _bw; \
    asm("cvt.rn.f16x2.f32 %0, %1, %2;" : "=r"(_bw) : "f"(_v1), "f"(_v0)); \
    Bw[(kpv) * AST + n] = _bw; }
#define B4(a)  BSTEP(a) BSTEP((a)+1) BSTEP((a)+2) BSTEP((a)+3)
#define B20(a) B4(a) B4((a)+4) B4((a)+8) B4((a)+12) B4((a)+16)

// k_main: per (c, e) CTA, 256 threads / 8 warps, 2 CTAs/SM.
// out4[64 x 64] = A[64 x 160] * B[160 x 64], split-fp16 A (hi+lo), fp16 B.
// A smem: word addr = kp*128 + ((col + 4*(kp&3)) & 63)*2 + sel (hi/lo).
// B smem: word addr = kp*72 + n. Node x lives in registers (xr[18]).
__global__ void __launch_bounds__(256, 2) k_main(const float* __restrict__ x,
                                                 float* __restrict__ out)
{
    extern __shared__ uint32_t sm[];
    uint32_t* Aw = sm + SM_A;
    uint32_t* Bw = sm + SM_B;
    float*    Cs = (float*)(sm + SM_C);

    const int c = blockIdx.x, e = blockIdx.y;
    const int tid  = threadIdx.x;
    const int lane = tid & 31, warp = tid >> 5;
    const int gid  = lane >> 2, tig = lane & 3;
    const int m_base = (warp & 3) * 16;
    const int n_base = (warp >> 2) * 32;

    const int n   = tid & 63;     // node column (build/epilogue)
    const int grp = tid >> 6;     // 4 groups x 20 kp rows; also epilogue m

    // --- one-time init: A tile load (rotated layout) ---
    {
        const uint4* srcA = (const uint4*)&g_A[(size_t)(e * C_N + c) * (KPN * 128)];
        for (int idx = tid; idx < KPN * 32; idx += 256) {
            int kp = idx >> 5, mp = idx & 31;          // mj pair index
            int mjp = (mp * 2 + 4 * (kp & 3)) & 63;    // rotated (stays even)
            *(uint4*)&Aw[kp * 128 + mjp * 2] = srcA[idx];
        }
    }

    const int cnt = g_cnt[e];
    const int* lst = &g_list[e * B_N];
    const int ntiles = (cnt + 63) >> 6;

    const int mjA0 = ((m_base + gid + 4 * tig) & 63) * 2;
    const int mjA1 = ((m_base + 8 + gid + 4 * tig) & 63) * 2;

    for (int t = 0; t < ntiles; t++) {
        __syncthreads();   // init done / previous tile fully consumed

        // --- load this thread's node row into registers ---
        const int idx = t * 64 + n;
        int b = -1;
        float xr[18];
#pragma unroll
        for (int q = 0; q < 18; q++) xr[q] = 0.f;
        if (idx < cnt) {
            b = lst[idx];
            const float4* xp = (const float4*)&x[((size_t)b * C_N + c) * 16];
            float4 v0 = xp[0], v1 = xp[1], v2 = xp[2], v3 = xp[3];
            xr[0]  = v0.x; xr[1]  = v0.y; xr[2]  = v0.z; xr[3]  = v0.w;
            xr[4]  = v1.x; xr[5]  = v1.y; xr[6]  = v1.z; xr[7]  = v1.w;
            xr[8]  = v2.x; xr[9]  = v2.y; xr[10] = v2.z; xr[11] = v2.w;
            xr[12] = v3.x; xr[13] = v3.y; xr[14] = v3.z; xr[15] = v3.w;
            xr[16] = 1.f;
        }

        // --- B build: 20 kp rows, compile-time indices, zero LDS ---
        switch (grp) {
            case 0: { B20(0)  } break;
            case 1: { B20(20) } break;
            case 2: { B20(40) } break;
            default:{ B20(60) } break;
        }
        __syncthreads();

        // --- tensor GEMM: 10 k16-steps, (Ah + Al) * B = 8 MMA/step ---
        float d[4][4];
#pragma unroll
        for (int nf = 0; nf < 4; nf++)
#pragma unroll
            for (int q = 0; q < 4; q++) d[nf][q] = 0.f;

#pragma unroll
        for (int ks = 0; ks < 10; ks++) {
            const int rA0 = (ks * 8 + tig) * 128;
            const int rA1 = (ks * 8 + 4 + tig) * 128;
            uint2 a0p = *(uint2*)&Aw[rA0 + mjA0];
            uint2 a1p = *(uint2*)&Aw[rA0 + mjA1];
            uint2 a2p = *(uint2*)&Aw[rA1 + mjA0];
            uint2 a3p = *(uint2*)&Aw[rA1 + mjA1];
            const int rB0 = (ks * 8 + tig) * AST;
            const int rB1 = (ks * 8 + 4 + tig) * AST;
#pragma unroll
            for (int nf = 0; nf < 4; nf++) {
                const int nn = n_base + nf * 8 + gid;
                uint32_t b0 = Bw[rB0 + nn];
                uint32_t b1 = Bw[rB1 + nn];
                mma_f16(d[nf], a0p.x, a1p.x, a2p.x, a3p.x, b0, b1);  // hi
                mma_f16(d[nf], a0p.y, a1p.y, a2p.y, a3p.y, b0, b1);  // lo
            }
        }

        // --- stash C ---
#pragma unroll
        for (int nf = 0; nf < 4; nf++) {
            const int nn = n_base + nf * 8 + 2 * tig;
            *(float2*)&Cs[(m_base + gid) * AST + nn]     = make_float2(d[nf][0], d[nf][1]);
            *(float2*)&Cs[(m_base + 8 + gid) * AST + nn] = make_float2(d[nf][2], d[nf][3]);
        }
        __syncthreads();

        // --- epilogue: out[m=grp, n] = sum_j C[m*16+j,n] * x_j (registers) ---
        if (b >= 0) {
            float s = 0.f;
#pragma unroll
            for (int j = 0; j < 16; j++)
                s += Cs[(grp * 16 + j) * AST + n] * xr[j];
            const int col = (grp == 0) ? c : (128 + c * 3 + (grp - 1));
            out[b * OUTW + col] = s;
        }
    }
}

// ---------------------------------------------------------------------------
extern "C" void kernel_launch(void* const* d_in, const int* in_sizes, int n_in,
                              void* d_out, int out_size)
{
    (void)in_sizes; (void)n_in; (void)out_size;
    const float* x    = (const float*)d_in[0];
    const float* y    = (const float*)d_in[1];
    const float* U3_0 = (const float*)d_in[2];
    const float* U2_0 = (const float*)d_in[3];
    const float* U1_0 = (const float*)d_in[4];
    const float* W3_0 = (const float*)d_in[5];
    const float* W2_0 = (const float*)d_in[6];
    const float* W1_0 = (const float*)d_in[7];
    const float* U3_1 = (const float*)d_in[8];
    const float* U2_1 = (const float*)d_in[9];
    const float* U1_1 = (const float*)d_in[10];
    const float* W3_1 = (const float*)d_in[11];
    const float* W2_1 = (const float*)d_in[12];
    const float* W1_1 = (const float*)d_in[13];

    const int smem_main = SM_WORDS * (int)sizeof(uint32_t);  // 82,432 B
    cudaFuncSetAttribute(k_main, cudaFuncAttributeMaxDynamicSharedMemorySize, smem_main);

    k_zero<<<1, 32>>>();
    k_group<<<(B_N + 255) / 256, 256>>>(y);
    k_prep3<<<dim3(KPN, 5), 256>>>(U3_0, U2_0, U1_0, W3_0, W2_0, W1_0,
                                   U3_1, U2_1, U1_1, W3_1, W2_1, W1_1);
    k_main<<<dim3(C_N, E_N), 256, smem_main>>>(x, (float*)d_out);
}